// round 15
// baseline (speedup 1.0000x reference)
#include <cuda_runtime.h>
#include <cstdint>

#define NN 2048
#define BSP 256
#define NB 8
#define THRESH 0.3f
#define OVERLAP 0.5f
#define NBUCK 512
#define EPER 256                       // per-lane edge cap (smem)
#define SORTCAP 64                     // sort (enable GS) only if cnt <= this
#define DYN_BYTES 73728
#define FULLM 0xFFFFFFFFu

__device__ int g_cnt[NB * 4];                      // zero-init; nms re-zeroes
__device__ unsigned long long g_key[NB * 4][NN];   // (score_bits<<32)|(2047-n)
__device__ float2 g_box[NB][NN];

// ---- prep: decode + softmax once per (b,n); warp-aggregated compaction ----
__global__ __launch_bounds__(BSP) void prep_kernel(
    const float* __restrict__ loc, const float* __restrict__ cls,
    const float* __restrict__ dflt)
{
    const int b = blockIdx.x >> 3;
    const int n = ((blockIdx.x & 7) << 8) | threadIdx.x;
    const int lane = threadIdx.x & 31;
    const float* locb = loc + (size_t)b * NN * 2;
    const float* clsb = cls + (size_t)b * NN * 5;

    float dc = dflt[2 * n], dw = dflt[2 * n + 1];
    float l0 = locb[2 * n], l1 = locb[2 * n + 1];
    float ctr = dc + l0 * dw;
    float w   = dw * expf(l1);
    g_box[b][n] = make_float2(ctr - 0.5f * w, ctr + 0.5f * w);

    float x0 = clsb[5 * n + 0];
    float x1 = clsb[5 * n + 1];
    float x2 = clsb[5 * n + 2];
    float x3 = clsb[5 * n + 3];
    float x4 = clsb[5 * n + 4];
    float mx = fmaxf(fmaxf(fmaxf(x0, x1), fmaxf(x2, x3)), x4);
    float e1 = expf(x1 - mx), e2 = expf(x2 - mx),
          e3 = expf(x3 - mx), e4 = expf(x4 - mx);
    float sum = expf(x0 - mx) + e1 + e2 + e3 + e4;
    float sc[4] = { e1 / sum, e2 / sum, e3 / sum, e4 / sum };

    #pragma unroll
    for (int c = 0; c < 4; c++) {
        bool v = sc[c] > THRESH;
        unsigned ball = __ballot_sync(FULLM, v);
        int cnt = __popc(ball);
        if (cnt) {
            int leader = __ffs(ball) - 1;
            int base = 0;
            if (lane == leader) base = atomicAdd(&g_cnt[b * 4 + c], cnt);
            base = __shfl_sync(FULLM, base, leader);
            if (v) {
                int off = __popc(ball & ((1u << lane) - 1u));
                g_key[b * 4 + c][base + off] =
                    ((unsigned long long)__float_as_uint(sc[c]) << 32)
                    | (unsigned int)(2047 - n);
            }
        }
    }
}

__device__ __forceinline__ unsigned fmap(float f) {
    unsigned u = __float_as_uint(f);
    return u ^ ((u & 0x80000000u) ? 0xFFFFFFFFu : 0x80000000u);
}
__device__ __forceinline__ float funmap(unsigned u) {
    unsigned v = u ^ ((u & 0x80000000u) ? 0x80000000u : 0xFFFFFFFFu);
    return __uint_as_float(v);
}

// ---- nms: ONE WARP per (b,c) problem ----
__global__ __launch_bounds__(32) void nms_kernel(float* __restrict__ out)
{
    extern __shared__ char dyn[];
    unsigned long long* s_key  = (unsigned long long*)(dyn);          // 16KB spatial keys
    float2*             s_sbox = (float2*)(dyn + 16384);              // 16KB
    float*              s_sc   = (float*)(dyn + 32768);               // 8KB
    unsigned int*       s_ep   = (unsigned int*)(dyn + 40960);        // 32KB edges [32][EPER]

    __shared__ unsigned int s_hist[NBUCK];
    __shared__ unsigned int s_bstart[NBUCK + 1];
    __shared__ unsigned int s_boff[NBUCK];
    __shared__ unsigned long long s_keepm[32];   // keep mask by rank-segment
    __shared__ unsigned long long s_supm[32];    // fallback sup mask
    __shared__ unsigned long long s_keepn[32];   // kept flags by original n
    __shared__ int s_ecnt[32];
    __shared__ int s_over;

    const int bc = blockIdx.x;
    const int b  = bc >> 2;
    const int lane = threadIdx.x;
    const int M = g_cnt[bc];

    if (lane == 0) s_over = 0;
    s_ecnt[lane] = 0;
    s_keepn[lane] = 0ull;
    for (int h = lane; h < NBUCK; h += 32) s_hist[h] = 0u;
    __syncwarp();

    // segment size L = 1<<Lsh, lane owns ranks [lane<<Lsh, (lane+1)<<Lsh)
    int Lsh = 0;
    while ((32 << Lsh) < M) Lsh++;               // M<=2048 -> Lsh<=6, L<=64
    const int L = 1 << Lsh;

    // ---- pass 1: min/max of start (register + butterfly reduce) ----
    unsigned mnv = 0xFFFFFFFFu, mxv = 0u;
    for (int s = lane; s < M; s += 32) {
        int n = 2047 - (int)(unsigned int)g_key[bc][s];
        unsigned fm = fmap(g_box[b][n].x);
        mnv = min(mnv, fm); mxv = max(mxv, fm);
    }
    #pragma unroll
    for (int o = 16; o; o >>= 1) {
        mnv = min(mnv, __shfl_xor_sync(FULLM, mnv, o));
        mxv = max(mxv, __shfl_xor_sync(FULLM, mxv, o));
    }
    const float mn = funmap(mnv);
    const float rng = funmap(mxv) - mn;
    const float scale = (rng > 0.0f) ? ((float)NBUCK / rng) : 0.0f;

    // ---- pass 2: histogram ----
    for (int s = lane; s < M; s += 32) {
        int n = 2047 - (int)(unsigned int)g_key[bc][s];
        int bu = (int)fminf((g_box[b][n].x - mn) * scale, (float)(NBUCK - 1));
        if (bu < 0) bu = 0;
        atomicAdd(&s_hist[bu], 1u);
    }
    __syncwarp();

    // ---- scan: 16 buckets per lane + warp scan ----
    {
        unsigned lsum = 0;
        #pragma unroll
        for (int i = 0; i < 16; i++) lsum += s_hist[lane * 16 + i];
        unsigned x = lsum;
        #pragma unroll
        for (int o = 1; o < 32; o <<= 1) {
            unsigned y = __shfl_up_sync(FULLM, x, o);
            if (lane >= o) x += y;
        }
        unsigned acc = x - lsum;                  // exclusive
        #pragma unroll
        for (int i = 0; i < 16; i++) {
            unsigned h = s_hist[lane * 16 + i];
            s_bstart[lane * 16 + i] = acc;
            s_boff[lane * 16 + i]   = acc;
            acc += h;
        }
        if (lane == 31) s_bstart[NBUCK] = acc;
    }
    __syncwarp();

    // ---- scatter into spatial (bucket) order ----
    for (int s = lane; s < M; s += 32) {
        unsigned long long k = g_key[bc][s];
        int n = 2047 - (int)(unsigned int)k;
        float2 bx = g_box[b][n];
        int bu = (int)fminf((bx.x - mn) * scale, (float)(NBUCK - 1));
        if (bu < 0) bu = 0;
        int pos = atomicAdd(&s_boff[bu], 1u);
        s_key[pos] = k;
        s_sbox[pos] = bx;
    }
    __syncwarp();

    // ---- pair scan -> per-target-owner edge lists ----
    for (int p = lane; p < M; p += 32) {
        float2 bp = s_sbox[p];
        unsigned long long kp = s_key[p];
        float lp = bp.y - bp.x;
        int be = (int)fminf((bp.y - mn) * scale, (float)(NBUCK - 1));
        if (be < 0) be = 0;
        int lim = (int)s_bstart[be + 1];
        for (int q = p + 1; q < lim; q++) {
            float2 bq = s_sbox[q];
            float inter = fmaxf(fminf(bp.y, bq.y) - fmaxf(bp.x, bq.x), 0.0f);
            float uni = lp + (bq.y - bq.x) - inter;
            float iou = inter / fmaxf(uni, 1e-12f);
            if (iou > OVERLAP) {
                int src, tgt;
                if (kp > s_key[q]) { src = p; tgt = q; }
                else               { src = q; tgt = p; }
                int owner = tgt >> Lsh;
                int sl = atomicAdd(&s_ecnt[owner], 1);
                if (sl < EPER)
                    s_ep[owner * EPER + sl] = ((unsigned)src << 6)
                                            | (unsigned)(tgt & (L - 1));
                else s_over = 1;
            }
        }
    }
    __syncwarp();

    const int cnt = (s_ecnt[lane] < EPER) ? s_ecnt[lane] : EPER;
    const int overflow = s_over;

    // valid mask for my segment
    int have = M - (lane << Lsh);
    if (have < 0) have = 0;
    if (have > L) have = L;
    const unsigned long long validL =
        (have >= 64) ? ~0ull : ((have > 0) ? ((1ull << have) - 1ull) : 0ull);

    // ---- sort my edges by target-local (enables in-lane Gauss-Seidel) ----
    bool gs_ok = (!overflow) && (cnt <= SORTCAP);
    if (gs_ok) {
        unsigned int* me = s_ep + lane * EPER;
        for (int i = 1; i < cnt; i++) {
            unsigned v = me[i];
            unsigned tv = v & 63u;
            int j = i - 1;
            while (j >= 0 && (me[j] & 63u) > tv) { me[j + 1] = me[j]; j--; }
            me[j + 1] = v;
        }
    }

    // ---- init keep ----
    unsigned long long keep = validL;
    s_keepm[lane] = validL;
    __syncwarp();

    // ---- warp-scope Jacobi (+ in-lane GS) to the greedy fixpoint ----
    for (int round = 0; round <= M; round++) {
        unsigned long long sup = 0ull;
        if (!overflow) {
            const unsigned int* me = s_ep + lane * EPER;
            for (int e = 0; e < cnt; e++) {
                unsigned ed = me[e];
                unsigned src = ed >> 6;
                unsigned tb  = ed & 63u;
                int so = src >> Lsh;
                unsigned sb = src & (L - 1);
                unsigned long long kv;
                if (gs_ok && so == lane && sb < tb)
                    kv = (validL >> sb) & ~(sup >> sb);   // fully resolved this round
                else
                    kv = s_keepm[so] >> sb;               // last round
                if (kv & 1ull) sup |= 1ull << tb;
            }
        } else {
            // exact fallback: window re-scan each round (never expected)
            if (lane == 0) { }
            s_supm[lane] = 0ull;
            __syncwarp();
            for (int p = lane; p < M; p += 32) {
                float2 bp = s_sbox[p];
                unsigned long long kp = s_key[p];
                float lp = bp.y - bp.x;
                int be = (int)fminf((bp.y - mn) * scale, (float)(NBUCK - 1));
                if (be < 0) be = 0;
                int lim = (int)s_bstart[be + 1];
                for (int q = p + 1; q < lim; q++) {
                    float2 bq = s_sbox[q];
                    float inter = fmaxf(fminf(bp.y, bq.y) - fmaxf(bp.x, bq.x), 0.0f);
                    float uni = lp + (bq.y - bq.x) - inter;
                    float iou = inter / fmaxf(uni, 1e-12f);
                    if (iou > OVERLAP) {
                        int src, tgt;
                        if (kp > s_key[q]) { src = p; tgt = q; }
                        else               { src = q; tgt = p; }
                        if ((s_keepm[src >> Lsh] >> (src & (L - 1))) & 1ull)
                            atomicOr(&s_supm[tgt >> Lsh],
                                     1ull << (tgt & (L - 1)));
                    }
                }
            }
            __syncwarp();
            sup = s_supm[lane];
        }

        unsigned long long nk = validL & ~sup;
        unsigned chg = __ballot_sync(FULLM, nk != keep);
        __syncwarp();            // all reads of s_keepm done before writes
        s_keepm[lane] = nk;
        keep = nk;
        __syncwarp();
        if (!chg) break;
    }

    // ---- scatter kept scores + kept-by-n flags ----
    for (int p = lane; p < M; p += 32) {
        if ((s_keepm[p >> Lsh] >> (p & (L - 1))) & 1ull) {
            unsigned long long k = s_key[p];
            int n = 2047 - (int)(unsigned int)k;
            s_sc[n] = __uint_as_float((unsigned int)(k >> 32));
            atomicOr(&s_keepn[n >> 6], 1ull << (n & 63));
        }
    }
    __syncwarp();

    // ---- output (in_range applied AFTER NMS, matching reference) ----
    float* ob = out + (size_t)bc * NN * 3;
    for (int n = lane; n < NN; n += 32) {
        float2 bx = g_box[b][n];
        bool kp = ((s_keepn[n >> 6] >> (n & 63)) & 1ull)
                  && (bx.x > -10.0f) && (bx.y < 10.0f);
        ob[3 * n + 0] = kp ? bx.x : 0.0f;
        ob[3 * n + 1] = kp ? bx.y : 0.0f;
        ob[3 * n + 2] = kp ? s_sc[n] : 0.0f;
    }

    // ---- self-restore: leave counter zeroed for the next replay ----
    if (lane == 0) g_cnt[bc] = 0;
}

extern "C" void kernel_launch(void* const* d_in, const int* in_sizes, int n_in,
                              void* d_out, int out_size) {
    const float* loc  = (const float*)d_in[0];  // (8,2048,2)
    const float* cls  = (const float*)d_in[1];  // (8,2048,5)
    const float* dflt = (const float*)d_in[2];  // (2048,2)
    float* out = (float*)d_out;                 // (8,4,2048,3)
    cudaFuncSetAttribute(nms_kernel, cudaFuncAttributeMaxDynamicSharedMemorySize,
                         DYN_BYTES);
    prep_kernel<<<64, BSP>>>(loc, cls, dflt);
    nms_kernel<<<32, 32, DYN_BYTES>>>(out);
}

// round 17
// speedup vs baseline: 1.7736x; 1.7736x over previous
#include <cuda_runtime.h>
#include <cstdint>

#define NN 2048
#define BS 256
#define NB 8
#define THRESH 0.3f
#define OVERLAP 0.5f
#define NBUCK 512
#define EPOOL 8192
#define FULLM 0xFFFFFFFFu

// dynamic smem layout
#define OFF_KEY    0          // u64[2048]  sorted spatial keys      16KB
#define OFF_SBOX   16384      // float2[2048] sorted boxes           16KB
#define OFF_SC     32768      // float[2048] kept scores by n         8KB
#define OFF_POOL   40960      // u32[8192] edge pool / key staging   32KB
#define OFF_EDGE   73728      // u16[8192] CSR edges / box staging   16KB
#define OFF_ESTART 90112      // u32[2049] CSR row starts           8.2KB
#define OFF_EOFF   98560      // u32[2048] CSR fill cursors           8KB
#define DYN_BYTES  106752

__device__ int g_cnt[NB * 4];                      // zero-init; nms re-zeroes
__device__ unsigned long long g_key[NB * 4][NN];   // (score_bits<<32)|(2047-n)
__device__ float2 g_box[NB][NN];

// ---- prep: decode + softmax once per (b,n); warp-aggregated compaction ----
__global__ __launch_bounds__(BS) void prep_kernel(
    const float* __restrict__ loc, const float* __restrict__ cls,
    const float* __restrict__ dflt)
{
    const int b = blockIdx.x >> 3;
    const int n = ((blockIdx.x & 7) << 8) | threadIdx.x;
    const int lane = threadIdx.x & 31;
    const float* locb = loc + (size_t)b * NN * 2;
    const float* clsb = cls + (size_t)b * NN * 5;

    float dc = dflt[2 * n], dw = dflt[2 * n + 1];
    float l0 = locb[2 * n], l1 = locb[2 * n + 1];
    float ctr = dc + l0 * dw;
    float w   = dw * expf(l1);
    g_box[b][n] = make_float2(ctr - 0.5f * w, ctr + 0.5f * w);

    float x0 = clsb[5 * n + 0];
    float x1 = clsb[5 * n + 1];
    float x2 = clsb[5 * n + 2];
    float x3 = clsb[5 * n + 3];
    float x4 = clsb[5 * n + 4];
    float mx = fmaxf(fmaxf(fmaxf(x0, x1), fmaxf(x2, x3)), x4);
    float e1 = expf(x1 - mx), e2 = expf(x2 - mx),
          e3 = expf(x3 - mx), e4 = expf(x4 - mx);
    float sum = expf(x0 - mx) + e1 + e2 + e3 + e4;
    float sc[4] = { e1 / sum, e2 / sum, e3 / sum, e4 / sum };

    #pragma unroll
    for (int c = 0; c < 4; c++) {
        bool v = sc[c] > THRESH;
        unsigned ball = __ballot_sync(FULLM, v);
        int cnt = __popc(ball);
        if (cnt) {
            int leader = __ffs(ball) - 1;
            int base = 0;
            if (lane == leader) base = atomicAdd(&g_cnt[b * 4 + c], cnt);
            base = __shfl_sync(FULLM, base, leader);
            if (v) {
                int off = __popc(ball & ((1u << lane) - 1u));
                g_key[b * 4 + c][base + off] =
                    ((unsigned long long)__float_as_uint(sc[c]) << 32)
                    | (unsigned int)(2047 - n);
            }
        }
    }
}

__device__ __forceinline__ unsigned fmap(float f) {
    unsigned u = __float_as_uint(f);
    return u ^ ((u & 0x80000000u) ? 0xFFFFFFFFu : 0x80000000u);
}
__device__ __forceinline__ float funmap(unsigned u) {
    unsigned v = u ^ ((u & 0x80000000u) ? 0x80000000u : 0xFFFFFFFFu);
    return __uint_as_float(v);
}
__device__ __forceinline__ unsigned long long seg_valid(int M, int seg,
                                                        int Lsh, int L) {
    int have = M - (seg << Lsh);
    if (have < 0) have = 0;
    if (have > L) have = L;
    return (have >= 64) ? ~0ull : ((have > 0) ? ((1ull << have) - 1ull) : 0ull);
}

// ---- nms: one CTA per (b,c); 256-thread front-end + warp-0 resolve ----
__global__ __launch_bounds__(BS) void nms_kernel(float* __restrict__ out)
{
    extern __shared__ char dyn[];
    unsigned long long* s_key  = (unsigned long long*)(dyn + OFF_KEY);
    float2*             s_sbox = (float2*)(dyn + OFF_SBOX);
    float*              s_sc   = (float*)(dyn + OFF_SC);
    unsigned int*       s_pool = (unsigned int*)(dyn + OFF_POOL);
    unsigned short*     s_edge = (unsigned short*)(dyn + OFF_EDGE);
    unsigned int*       s_estart = (unsigned int*)(dyn + OFF_ESTART);
    unsigned int*       s_eoff   = (unsigned int*)(dyn + OFF_EOFF);
    // front-end staging overlays (consumed before pool/edge arrays are written)
    unsigned long long* s_kstage = (unsigned long long*)(dyn + OFF_POOL);
    float2*             s_bstage = (float2*)(dyn + OFF_EDGE);

    __shared__ unsigned int s_hist[NBUCK];
    __shared__ unsigned int s_bstart[NBUCK + 1];
    __shared__ unsigned int s_boff[NBUCK];
    __shared__ unsigned int s_wsum[8];
    __shared__ unsigned long long s_keepm[32];   // keep mask by spatial segment
    __shared__ unsigned long long s_supm[32];    // fallback sup mask
    __shared__ unsigned long long s_keepn[32];   // kept flags by original n
    __shared__ unsigned int s_minu, s_maxu;
    __shared__ int s_ne, s_over, s_chg;

    const int bc = blockIdx.x;
    const int b  = bc >> 2;
    const int tid = threadIdx.x;
    const int lane = tid & 31, wid = tid >> 5;
    const int M = g_cnt[bc];

    if (tid == 0) { s_ne = 0; s_over = 0; s_minu = 0xFFFFFFFFu; s_maxu = 0u; }
    if (tid < 32) s_keepn[tid] = 0ull;
    for (int h = tid; h < NBUCK; h += BS) s_hist[h] = 0u;
    __syncthreads();

    int Lsh = 0;
    while ((32 << Lsh) < M) Lsh++;       // 32 segments cover M; L <= 64
    const int L = 1 << Lsh;

    // ---- stage keys+boxes, min/max start ----
    for (int s = tid; s < M; s += BS) {
        unsigned long long k = g_key[bc][s];
        int n = 2047 - (int)(unsigned int)k;
        float2 bx = g_box[b][n];
        s_kstage[s] = k;
        s_bstage[s] = bx;
        unsigned fm = fmap(bx.x);
        atomicMin(&s_minu, fm);
        atomicMax(&s_maxu, fm);
    }
    __syncthreads();

    const float mn = funmap(s_minu);
    const float rng = funmap(s_maxu) - mn;
    const float scale = (rng > 0.0f) ? ((float)NBUCK / rng) : 0.0f;

    // ---- histogram by start bucket ----
    for (int s = tid; s < M; s += BS) {
        int bu = (int)fminf((s_bstage[s].x - mn) * scale, (float)(NBUCK - 1));
        if (bu < 0) bu = 0;
        atomicAdd(&s_hist[bu], 1u);
    }
    __syncthreads();

    // ---- exclusive scan over 512 bins (2 per thread) ----
    {
        unsigned v0 = s_hist[2 * tid], v1 = s_hist[2 * tid + 1];
        unsigned x = v0 + v1;
        #pragma unroll
        for (int o = 1; o < 32; o <<= 1) {
            unsigned y = __shfl_up_sync(FULLM, x, o);
            if (lane >= o) x += y;
        }
        if (lane == 31) s_wsum[wid] = x;
        __syncthreads();
        if (tid == 0) {
            unsigned acc = 0;
            for (int w2 = 0; w2 < 8; w2++) { unsigned t = s_wsum[w2]; s_wsum[w2] = acc; acc += t; }
            s_bstart[NBUCK] = acc;
        }
        __syncthreads();
        unsigned excl = x + s_wsum[wid] - (v0 + v1);
        s_bstart[2 * tid] = excl;          s_boff[2 * tid] = excl;
        s_bstart[2 * tid + 1] = excl + v0; s_boff[2 * tid + 1] = excl + v0;
    }
    __syncthreads();

    // ---- scatter into spatial (bucket) order + zero CSR counts ----
    for (int s = tid; s < M; s += BS) {
        float2 bx = s_bstage[s];
        int bu = (int)fminf((bx.x - mn) * scale, (float)(NBUCK - 1));
        if (bu < 0) bu = 0;
        int pos = atomicAdd(&s_boff[bu], 1u);
        s_key[pos] = s_kstage[s];
        s_sbox[pos] = bx;
    }
    for (int i = tid; i <= NN; i += BS) s_estart[i] = 0u;
    __syncthreads();

    // ---- pair scan -> edge pool + per-target in-degree ----
    for (int p = tid; p < M; p += BS) {
        float2 bp = s_sbox[p];
        unsigned long long kp = s_key[p];
        float lp = bp.y - bp.x;
        int be = (int)fminf((bp.y - mn) * scale, (float)(NBUCK - 1));
        if (be < 0) be = 0;
        int lim = (int)s_bstart[be + 1];
        for (int q = p + 1; q < lim; q++) {
            float2 bq = s_sbox[q];
            float inter = fmaxf(fminf(bp.y, bq.y) - fmaxf(bp.x, bq.x), 0.0f);
            float uni = lp + (bq.y - bq.x) - inter;
            float iou = inter / fmaxf(uni, 1e-12f);
            if (iou > OVERLAP) {
                int src, tgt;
                if (kp > s_key[q]) { src = p; tgt = q; }
                else               { src = q; tgt = p; }
                int sl = atomicAdd(&s_ne, 1);
                if (sl < EPOOL) {
                    s_pool[sl] = ((unsigned)src << 16) | (unsigned)tgt;
                    atomicAdd(&s_estart[tgt], 1u);
                } else s_over = 1;
            }
        }
    }
    __syncthreads();
    const int ne = (s_ne < EPOOL) ? s_ne : EPOOL;
    const int overflow = s_over;

    // ---- block exclusive scan of in-degrees -> CSR row starts ----
    {
        unsigned loc[8]; unsigned ssum = 0;
        #pragma unroll
        for (int i = 0; i < 8; i++) { loc[i] = s_estart[tid * 8 + i]; ssum += loc[i]; }
        unsigned x = ssum;
        #pragma unroll
        for (int o = 1; o < 32; o <<= 1) {
            unsigned y = __shfl_up_sync(FULLM, x, o);
            if (lane >= o) x += y;
        }
        if (lane == 31) s_wsum[wid] = x;
        __syncthreads();
        if (tid == 0) {
            unsigned acc = 0;
            for (int w2 = 0; w2 < 8; w2++) { unsigned t = s_wsum[w2]; s_wsum[w2] = acc; acc += t; }
        }
        __syncthreads();
        unsigned base = x - ssum + s_wsum[wid];
        #pragma unroll
        for (int i = 0; i < 8; i++) {
            unsigned h = loc[i];
            s_estart[tid * 8 + i] = base;
            s_eoff[tid * 8 + i]   = base;
            base += h;
        }
        if (tid == 255) s_estart[NN] = base;
    }
    __syncthreads();

    // ---- scatter edges into CSR (grouped by target) ----
    for (int e = tid; e < ne; e += BS) {
        unsigned ed = s_pool[e];
        unsigned tgt = ed & 0xFFFFu;
        int pos = atomicAdd(&s_eoff[tgt], 1u);
        s_edge[pos] = (unsigned short)(ed >> 16);
    }
    if (tid < 32) s_keepm[tid] = seg_valid(M, tid, Lsh, L);
    __syncthreads();

    if (!overflow) {
        // ==== warp-0 resolve: Jacobi across segments + exact in-lane GS ====
        if (wid == 0) {
            const int base_p = lane << Lsh;
            const unsigned long long validL = seg_valid(M, lane, Lsh, L);
            int have = M - base_p;
            if (have < 0) have = 0;
            if (have > L) have = L;
            unsigned long long keep = validL;

            for (int round = 0; round <= M; round++) {
                unsigned long long sup = 0ull;
                for (int t = 0; t < have; t++) {
                    unsigned e0 = s_estart[base_p + t];
                    unsigned e1 = s_estart[base_p + t + 1];
                    for (unsigned e = e0; e < e1; e++) {
                        unsigned src = s_edge[e];
                        int so = src >> Lsh;
                        unsigned sb = src & (unsigned)(L - 1);
                        unsigned long long kv;
                        if (so == lane && sb < (unsigned)t)
                            kv = (validL & ~sup) >> sb;   // resolved this round
                        else
                            kv = s_keepm[so] >> sb;       // previous round
                        if (kv & 1ull) { sup |= 1ull << t; break; }
                    }
                }
                unsigned long long nk = validL & ~sup;
                unsigned chg = __ballot_sync(FULLM, nk != keep);
                s_keepm[lane] = nk;      // ballot synced all reads above
                keep = nk;
                __syncwarp();            // writes visible before next round
                if (!chg) break;
            }
        }
        __syncthreads();                 // warps 1-7 park here
    } else {
        // ==== exact fallback: block-wide re-scan Jacobi (never expected) ====
        for (int round = 0; round <= M; round++) {
            if (tid < 32) s_supm[tid] = 0ull;
            if (tid == 0) s_chg = 0;
            __syncthreads();
            for (int p = tid; p < M; p += BS) {
                float2 bp = s_sbox[p];
                unsigned long long kp = s_key[p];
                float lp = bp.y - bp.x;
                int be = (int)fminf((bp.y - mn) * scale, (float)(NBUCK - 1));
                if (be < 0) be = 0;
                int lim = (int)s_bstart[be + 1];
                for (int q = p + 1; q < lim; q++) {
                    float2 bq = s_sbox[q];
                    float inter = fmaxf(fminf(bp.y, bq.y) - fmaxf(bp.x, bq.x), 0.0f);
                    float uni = lp + (bq.y - bq.x) - inter;
                    float iou = inter / fmaxf(uni, 1e-12f);
                    if (iou > OVERLAP) {
                        int src, tgt;
                        if (kp > s_key[q]) { src = p; tgt = q; }
                        else               { src = q; tgt = p; }
                        if ((s_keepm[src >> Lsh] >> (src & (L - 1))) & 1ull)
                            atomicOr(&s_supm[tgt >> Lsh], 1ull << (tgt & (L - 1)));
                    }
                }
            }
            __syncthreads();
            if (tid < 32) {
                unsigned long long nv = seg_valid(M, tid, Lsh, L) & ~s_supm[tid];
                if (nv != s_keepm[tid]) s_chg = 1;
                s_keepm[tid] = nv;
            }
            __syncthreads();
            if (!s_chg) break;
        }
    }

    // ---- scatter kept scores + kept-by-n flags ----
    for (int p = tid; p < M; p += BS) {
        if ((s_keepm[p >> Lsh] >> (p & (L - 1))) & 1ull) {
            unsigned long long k = s_key[p];
            int n = 2047 - (int)(unsigned int)k;
            s_sc[n] = __uint_as_float((unsigned int)(k >> 32));
            atomicOr(&s_keepn[n >> 6], 1ull << (n & 63));
        }
    }
    __syncthreads();

    // ---- output (in_range applied AFTER NMS, matching reference) ----
    float* ob = out + (size_t)bc * NN * 3;
    for (int n = tid; n < NN; n += BS) {
        float2 bx = g_box[b][n];
        bool kp = ((s_keepn[n >> 6] >> (n & 63)) & 1ull)
                  && (bx.x > -10.0f) && (bx.y < 10.0f);
        ob[3 * n + 0] = kp ? bx.x : 0.0f;
        ob[3 * n + 1] = kp ? bx.y : 0.0f;
        ob[3 * n + 2] = kp ? s_sc[n] : 0.0f;
    }

    // ---- self-restore: leave counter zeroed for the next replay ----
    if (tid == 0) g_cnt[bc] = 0;
}

extern "C" void kernel_launch(void* const* d_in, const int* in_sizes, int n_in,
                              void* d_out, int out_size) {
    const float* loc  = (const float*)d_in[0];  // (8,2048,2)
    const float* cls  = (const float*)d_in[1];  // (8,2048,5)
    const float* dflt = (const float*)d_in[2];  // (2048,2)
    float* out = (float*)d_out;                 // (8,4,2048,3)
    cudaFuncSetAttribute(nms_kernel, cudaFuncAttributeMaxDynamicSharedMemorySize,
                         DYN_BYTES);
    prep_kernel<<<64, BS>>>(loc, cls, dflt);
    nms_kernel<<<32, BS, DYN_BYTES>>>(out);
}